// round 1
// baseline (speedup 1.0000x reference)
#include <cuda_runtime.h>
#include <math.h>

// Problem dims (fixed by the dataset)
#define BB   16
#define NQ   1024
#define MKV  1024
#define DD   768
#define SCALE 0.03608439182435161f   // 768^-0.5

// ---------------- scratch (device globals; no allocs allowed) ----------------
__device__ float g_A[2][DD * DD];                      // A_k = U^T diag(S_k^2) U
__device__ float g_xk[2][BB * NQ * DD];                // x @ A_k
__device__ float g_pos[NQ * MKV];                      // softmax(coords @ pos_emb)
__device__ float g_s[(size_t)BB * 2 * NQ * MKV];       // raw scaled scores
__device__ float g_attnc[(size_t)BB * NQ * MKV];       // routed attention

// ---------------- 64x64x16 fp32 tile microkernel ----------------
// smem tiles stored K-major: dst[16][68] (pad 68 keeps 16B alignment, spreads banks)

__device__ __forceinline__ void load_T(float dst[16][68], const float* __restrict__ src,
                                       int ld, int tid) {
    // src points at tile origin (row0, k0); rows are the 64-dim, k contiguous
    int r = tid >> 2;
    int g = (tid & 3) << 2;
    float4 v = *(const float4*)(src + (size_t)r * ld + g);
    dst[g + 0][r] = v.x; dst[g + 1][r] = v.y; dst[g + 2][r] = v.z; dst[g + 3][r] = v.w;
}

__device__ __forceinline__ void load_N(float dst[16][68], const float* __restrict__ src,
                                       int ld, int tid) {
    // src points at tile origin (k0, col0); k rows (16), cols contiguous (64)
    int kk = tid >> 4;
    int c  = (tid & 15) << 2;
    *(float4*)&dst[kk][c] = *(const float4*)(src + (size_t)kk * ld + c);
}

__device__ __forceinline__ void mm_tile(const float As[16][68], const float Bs[16][68],
                                        float acc[4][4], int tx, int ty) {
#pragma unroll
    for (int kk = 0; kk < 16; ++kk) {
        float4 a4 = *(const float4*)&As[kk][ty << 2];
        float4 b4 = *(const float4*)&Bs[kk][tx << 2];
        float a[4] = {a4.x, a4.y, a4.z, a4.w};
        float b[4] = {b4.x, b4.y, b4.z, b4.w};
#pragma unroll
        for (int i = 0; i < 4; ++i)
#pragma unroll
            for (int j = 0; j < 4; ++j)
                acc[i][j] = fmaf(a[i], b[j], acc[i][j]);
    }
}

// ---------------- K0: A_k = U^T diag(S_k^2) U ----------------
__global__ void k_buildA(const float* __restrict__ U, const float* __restrict__ S1,
                         const float* __restrict__ S2) {
    int kz = blockIdx.z;
    const float* S = kz ? S2 : S1;
    int j0 = blockIdx.y << 6, i0 = blockIdx.x << 6;
    __shared__ float As[16][68], Bs[16][68];
    int tid = threadIdx.x, tx = tid & 15, ty = tid >> 4;
    float acc[4][4] = {};
    for (int t0 = 0; t0 < DD; t0 += 16) {
        {
            int kk = tid >> 4, c = (tid & 15) << 2;
            int t = t0 + kk;
            float s = S[t]; float s2 = s * s;
            float4 a = *(const float4*)(U + (size_t)t * DD + j0 + c);
            a.x *= s2; a.y *= s2; a.z *= s2; a.w *= s2;
            *(float4*)&As[kk][c] = a;
            *(float4*)&Bs[kk][c] = *(const float4*)(U + (size_t)t * DD + i0 + c);
        }
        __syncthreads();
        mm_tile(As, Bs, acc, tx, ty);
        __syncthreads();
    }
    float* C = g_A[kz];
#pragma unroll
    for (int i = 0; i < 4; ++i) {
        float4 v = make_float4(acc[i][0], acc[i][1], acc[i][2], acc[i][3]);
        *(float4*)&C[(size_t)(j0 + (ty << 2) + i) * DD + i0 + (tx << 2)] = v;
    }
}

// ---------------- K1: x_k = x @ A_k  (NN gemm, M=16384,K=768,N=768) ----------------
__global__ void k_xk(const float* __restrict__ x) {
    int k = blockIdx.z;
    int row0 = blockIdx.y << 6, col0 = blockIdx.x << 6;
    __shared__ float As[16][68], Bs[16][68];
    int tid = threadIdx.x, tx = tid & 15, ty = tid >> 4;
    float acc[4][4] = {};
    const float* Bm = g_A[k];
    for (int k0 = 0; k0 < DD; k0 += 16) {
        load_T(As, x + (size_t)row0 * DD + k0, DD, tid);
        load_N(Bs, Bm + (size_t)k0 * DD + col0, DD, tid);
        __syncthreads();
        mm_tile(As, Bs, acc, tx, ty);
        __syncthreads();
    }
    float* C = g_xk[k];
#pragma unroll
    for (int i = 0; i < 4; ++i) {
        float4 v = make_float4(acc[i][0], acc[i][1], acc[i][2], acc[i][3]);
        *(float4*)&C[(size_t)(row0 + (ty << 2) + i) * DD + col0 + (tx << 2)] = v;
    }
}

// ---------------- K2: pos softmax rows ----------------
__global__ void k_pos(const float* __restrict__ coords, const float* __restrict__ pe,
                      float* __restrict__ /*unused*/ dummy) {
    int n = blockIdx.x;
    int tid = threadIdx.x;
    __shared__ float red[16];
    float p[6];
#pragma unroll
    for (int c = 0; c < 6; ++c) p[c] = pe[n * 6 + c];
    float v[4];
#pragma unroll
    for (int i = 0; i < 4; ++i) {
        int m = tid + (i << 8);
        const float* cr = coords + ((size_t)n * MKV + m) * 6;
        v[i] = cr[0]*p[0] + cr[1]*p[1] + cr[2]*p[2] + cr[3]*p[3] + cr[4]*p[4] + cr[5]*p[5];
    }
    // block max
    float mx = fmaxf(fmaxf(v[0], v[1]), fmaxf(v[2], v[3]));
#pragma unroll
    for (int o = 16; o; o >>= 1) mx = fmaxf(mx, __shfl_xor_sync(0xffffffffu, mx, o));
    int w = tid >> 5, lane = tid & 31;
    if (lane == 0) red[w] = mx;
    __syncthreads();
    mx = red[0];
#pragma unroll
    for (int i = 1; i < 8; ++i) mx = fmaxf(mx, red[i]);
    __syncthreads();
    float e = 0.f;
#pragma unroll
    for (int i = 0; i < 4; ++i) { v[i] = __expf(v[i] - mx); e += v[i]; }
#pragma unroll
    for (int o = 16; o; o >>= 1) e += __shfl_xor_sync(0xffffffffu, e, o);
    if (lane == 0) red[w] = e;
    __syncthreads();
    e = 0.f;
#pragma unroll
    for (int i = 0; i < 8; ++i) e += red[i];
    float rinv = __frcp_rn(e);
#pragma unroll
    for (int i = 0; i < 4; ++i) {
        int m = tid + (i << 8);
        g_pos[(size_t)n * MKV + m] = v[i] * rinv;
    }
    (void)dummy;
}

// ---------------- K3: scores s[b,k,n,m] = scale * <x_k[b,n], y[b,m]>  (NT gemm) ----------------
__global__ void k_scores(const float* __restrict__ y) {
    int z = blockIdx.z; int b = z >> 1; int k = z & 1;
    int n0 = blockIdx.y << 6, m0 = blockIdx.x << 6;
    __shared__ float As[16][68], Bs[16][68];
    int tid = threadIdx.x, tx = tid & 15, ty = tid >> 4;
    float acc[4][4] = {};
    const float* A = g_xk[k] + (size_t)b * NQ * DD;
    const float* Y = y + (size_t)b * MKV * DD;
    for (int k0 = 0; k0 < DD; k0 += 16) {
        load_T(As, A + (size_t)n0 * DD + k0, DD, tid);
        load_T(Bs, Y + (size_t)m0 * DD + k0, DD, tid);
        __syncthreads();
        mm_tile(As, Bs, acc, tx, ty);
        __syncthreads();
    }
    float* C = g_s + ((size_t)(b * 2 + k) * NQ) * MKV;
#pragma unroll
    for (int i = 0; i < 4; ++i) {
        float4 v = make_float4(acc[i][0] * SCALE, acc[i][1] * SCALE,
                               acc[i][2] * SCALE, acc[i][3] * SCALE);
        *(float4*)&C[(size_t)(n0 + (ty << 2) + i) * MKV + m0 + (tx << 2)] = v;
    }
}

// ---------------- K4: softmax + mix + entropy + route; writes attn_c and heat ----------------
__device__ __forceinline__ void blockReduce2(float& a, float& b, bool domax, float* red) {
#pragma unroll
    for (int o = 16; o; o >>= 1) {
        float ta = __shfl_xor_sync(0xffffffffu, a, o);
        float tb = __shfl_xor_sync(0xffffffffu, b, o);
        if (domax) { a = fmaxf(a, ta); b = fmaxf(b, tb); }
        else       { a += ta;          b += tb; }
    }
    int w = threadIdx.x >> 5, lane = threadIdx.x & 31;
    __syncthreads();                       // protect re-use of red[]
    if (lane == 0) { red[w] = a; red[8 + w] = b; }
    __syncthreads();
    a = red[0]; b = red[8];
#pragma unroll
    for (int i = 1; i < 8; ++i) {
        if (domax) { a = fmaxf(a, red[i]); b = fmaxf(b, red[8 + i]); }
        else       { a += red[i];          b += red[8 + i]; }
    }
}

__global__ void k_route(const float* __restrict__ gate, const float* __restrict__ temp,
                        float* __restrict__ heat_out) {
    int n = blockIdx.x, b = blockIdx.y;
    int tid = threadIdx.x;
    __shared__ float red[16];
    const float* s1 = g_s + ((size_t)(b * 2 + 0) * NQ + n) * MKV;
    const float* s2 = g_s + ((size_t)(b * 2 + 1) * NQ + n) * MKV;
    const float* pp = g_pos + (size_t)n * MKV;
    float v1[4], v2[4], pv[4];
#pragma unroll
    for (int i = 0; i < 4; ++i) {
        int m = tid + (i << 8);
        v1[i] = s1[m]; v2[i] = s2[m]; pv[i] = pp[m];
    }
    float m1 = -1e30f, m2 = -1e30f;
#pragma unroll
    for (int i = 0; i < 4; ++i) { m1 = fmaxf(m1, v1[i]); m2 = fmaxf(m2, v2[i]); }
    blockReduce2(m1, m2, true, red);
    float e1 = 0.f, e2 = 0.f;
#pragma unroll
    for (int i = 0; i < 4; ++i) {
        v1[i] = __expf(v1[i] - m1); e1 += v1[i];
        v2[i] = __expf(v2[i] - m2); e2 += v2[i];
    }
    blockReduce2(e1, e2, false, red);
    float r1 = __frcp_rn(e1), r2 = __frcp_rn(e2);
    float gg = gate[0];
    float gsig = 1.f / (1.f + __expf(-gg));
    float og = 1.f - gsig;
    float ent1 = 0.f, ent2 = 0.f;
#pragma unroll
    for (int i = 0; i < 4; ++i) {
        float a1 = og * v1[i] * r1 + gsig * pv[i];
        float a2 = og * v2[i] * r2 + gsig * pv[i];
        v1[i] = a1; v2[i] = a2;
        ent1 -= a1 * __logf(a1 + 1e-8f);
        ent2 -= a2 * __logf(a2 + 1e-8f);
    }
    blockReduce2(ent1, ent2, false, red);
    float tt = temp[0];
    float h1 = 2.f - 2.f / (1.f + __expf(-tt * ent1));
    float h2 = 2.f - 2.f / (1.f + __expf(-tt * ent2));
    bool fg = (h1 >= h2);
    if (tid == 0) heat_out[(size_t)b * NQ + n] = fg ? h1 : h2;
    float* ac = g_attnc + ((size_t)b * NQ + n) * MKV;
#pragma unroll
    for (int i = 0; i < 4; ++i) {
        int m = tid + (i << 8);
        ac[m] = fg ? v1[i] : v2[i];
    }
}

// ---------------- K5: out = attn_c @ y  (NN gemm per batch, K=1024) ----------------
__global__ void k_av(const float* __restrict__ y, float* __restrict__ out) {
    int b = blockIdx.z;
    int n0 = blockIdx.y << 6, c0 = blockIdx.x << 6;
    __shared__ float As[16][68], Bs[16][68];
    int tid = threadIdx.x, tx = tid & 15, ty = tid >> 4;
    float acc[4][4] = {};
    const float* A  = g_attnc + (size_t)b * NQ * MKV;
    const float* Bm = y + (size_t)b * MKV * DD;
    float* C = out + (size_t)b * NQ * DD;
    for (int k0 = 0; k0 < MKV; k0 += 16) {
        load_T(As, A + (size_t)n0 * MKV + k0, MKV, tid);
        load_N(Bs, Bm + (size_t)k0 * DD + c0, DD, tid);
        __syncthreads();
        mm_tile(As, Bs, acc, tx, ty);
        __syncthreads();
    }
#pragma unroll
    for (int i = 0; i < 4; ++i) {
        float4 v = make_float4(acc[i][0], acc[i][1], acc[i][2], acc[i][3]);
        *(float4*)&C[(size_t)(n0 + (ty << 2) + i) * DD + c0 + (tx << 2)] = v;
    }
}

// ---------------- launch ----------------
extern "C" void kernel_launch(void* const* d_in, const int* in_sizes, int n_in,
                              void* d_out, int out_size) {
    const float* x      = (const float*)d_in[0];
    const float* y      = (const float*)d_in[1];
    const float* coords = (const float*)d_in[2];
    const float* U      = (const float*)d_in[3];
    const float* S1     = (const float*)d_in[4];
    const float* S2     = (const float*)d_in[5];
    const float* gating = (const float*)d_in[6];
    const float* temp   = (const float*)d_in[7];
    const float* pe     = (const float*)d_in[8];
    float* out  = (float*)d_out;                          // [B,N,D]
    float* heat = out + (size_t)BB * NQ * DD;             // [B,N,1] appended

    k_buildA<<<dim3(DD / 64, DD / 64, 2), 256>>>(U, S1, S2);
    k_xk    <<<dim3(DD / 64, (BB * NQ) / 64, 2), 256>>>(x);
    k_pos   <<<dim3(NQ), 256>>>(coords, pe, nullptr);
    k_scores<<<dim3(MKV / 64, NQ / 64, BB * 2), 256>>>(y);
    k_route <<<dim3(NQ, BB), 256>>>(gating, temp, heat);
    k_av    <<<dim3(DD / 64, NQ / 64, BB), 256>>>(y, out);
}

// round 2
// speedup vs baseline: 3.6408x; 3.6408x over previous
#include <cuda_runtime.h>
#include <cuda_bf16.h>
#include <math.h>

#define BB   16
#define NQ   1024
#define MKV  1024
#define DD   768
#define SCALE 0.03608439182435161f   // 768^-0.5

// ---------------- scratch (device globals) ----------------
__device__ __nv_bfloat16 g_Ah[2][DD * DD], g_Al[2][DD * DD];
__device__ __nv_bfloat16 g_xh[BB * NQ * DD], g_xl[BB * NQ * DD];
__device__ __nv_bfloat16 g_yh[BB * MKV * DD], g_yl[BB * MKV * DD];
__device__ __nv_bfloat16 g_xkh[2][BB * NQ * DD], g_xkl[2][BB * NQ * DD];
__device__ float g_pos[NQ * MKV];
__device__ float g_s[(size_t)BB * 2 * NQ * MKV];
__device__ __nv_bfloat16 g_ach[(size_t)BB * NQ * MKV], g_acl[(size_t)BB * NQ * MKV];

// ---------------- PTX helpers ----------------
__device__ __forceinline__ unsigned u32smem(const void* p) {
    return (unsigned)__cvta_generic_to_shared(p);
}
#define CP16(dst, src) asm volatile("cp.async.cg.shared.global [%0], [%1], 16;\n" :: "r"(dst), "l"(src))
#define CPCOMMIT() asm volatile("cp.async.commit_group;\n" ::: "memory")
#define CPWAIT2() asm volatile("cp.async.wait_group 2;\n" ::: "memory")
#define LDSM4(R0,R1,R2,R3,addr) \
    asm volatile("ldmatrix.sync.aligned.m8n8.x4.shared.b16 {%0,%1,%2,%3}, [%4];" \
                 : "=r"(R0),"=r"(R1),"=r"(R2),"=r"(R3) : "r"(addr))
#define LDSM4T(R0,R1,R2,R3,addr) \
    asm volatile("ldmatrix.sync.aligned.m8n8.x4.trans.shared.b16 {%0,%1,%2,%3}, [%4];" \
                 : "=r"(R0),"=r"(R1),"=r"(R2),"=r"(R3) : "r"(addr))
#define MMA(C,A,B) \
    asm volatile("mma.sync.aligned.m16n8k16.row.col.f32.bf16.bf16.f32 " \
                 "{%0,%1,%2,%3},{%4,%5,%6,%7},{%8,%9},{%0,%1,%2,%3};" \
                 : "+f"((C)[0]),"+f"((C)[1]),"+f"((C)[2]),"+f"((C)[3]) \
                 : "r"((A)[0]),"r"((A)[1]),"r"((A)[2]),"r"((A)[3]),"r"((B)[0]),"r"((B)[1]))

__device__ __forceinline__ void split2(float a, float b, __nv_bfloat162& hi, __nv_bfloat162& lo) {
    __nv_bfloat16 h0 = __float2bfloat16(a), h1 = __float2bfloat16(b);
    __nv_bfloat16 l0 = __float2bfloat16(a - __bfloat162float(h0));
    __nv_bfloat16 l1 = __float2bfloat16(b - __bfloat162float(h1));
    hi.x = h0; hi.y = h1; lo.x = l0; lo.y = l1;
}

// ---------------- bf16-split GEMM mainloop ----------------
// Block tile 128x128, K-chunk 32, 3-stage cp.async pipeline, 8 warps (2Mx4N).
// A layout: [M][K] bf16 (hi+lo). B: BT ? [K][N] (trans ldmatrix) : [N][K].
// smem: A stage = 128 rows * stride 40 bf16 = 10240 B
//       B NT stage = 10240 B;  B NN stage = 32 rows * stride 136 bf16 = 8704 B

template<bool BT>
__device__ __forceinline__ void gemm_main(
    const __nv_bfloat16* __restrict__ Ah, const __nv_bfloat16* __restrict__ Al, int lda,
    const __nv_bfloat16* __restrict__ Bh, const __nv_bfloat16* __restrict__ Bl, int ldb,
    int K, int row0, int col0, float acc[4][4][4])
{
    extern __shared__ char smc[];
    const unsigned BSTG = BT ? 8704u : 10240u;
    const unsigned oAl = 30720u;            // A hi at 0, lo at 3*10240
    const unsigned oBh = 61440u;
    const unsigned oBl = 61440u + 3u * BSTG;
    unsigned sb = u32smem(smc);
    int tid = threadIdx.x;
    int KT = K >> 5;

    auto load_stage = [&](int s, int kt) {
        if (kt < KT) {
            int k0 = kt << 5;
#pragma unroll
            for (int i = 0; i < 2; ++i) {           // A: 2 chunks hi + 2 lo per thread
                int c = tid * 2 + i, rr = c >> 2, ch = c & 3;
                size_t go = (size_t)(row0 + rr) * lda + k0 + ch * 8;
                unsigned d = sb + (unsigned)(s * 10240 + rr * 80 + ch * 16);
                CP16(d, Ah + go);
                CP16(d + oAl, Al + go);
            }
#pragma unroll
            for (int i = 0; i < 2; ++i) {           // B
                int c = tid * 2 + i;
                if (BT) {
                    int kr = c >> 4, ch = c & 15;
                    size_t go = (size_t)(k0 + kr) * ldb + col0 + ch * 8;
                    unsigned d = sb + oBh + (unsigned)(s * 8704 + kr * 272 + ch * 16);
                    CP16(d, Bh + go);
                    CP16(d + 3u * 8704u, Bl + go);
                } else {
                    int rr = c >> 2, ch = c & 3;
                    size_t go = (size_t)(col0 + rr) * ldb + k0 + ch * 8;
                    unsigned d = sb + oBh + (unsigned)(s * 10240 + rr * 80 + ch * 16);
                    CP16(d, Bh + go);
                    CP16(d + 3u * 10240u, Bl + go);
                }
            }
        }
        CPCOMMIT();
    };

    load_stage(0, 0);
    load_stage(1, 1);

    int lane = tid & 31, wid = tid >> 5;
    int wm = wid & 1, wn = wid >> 1;
    int r = lane & 7, sel = lane >> 3, sx = sel & 1, sy = sel >> 1;

    for (int kt = 0; kt < KT; ++kt) {
        load_stage((kt + 2) % 3, kt + 2);
        CPWAIT2();
        __syncthreads();
        int s = kt % 3;
        unsigned aBase = sb + (unsigned)(s * 10240);
        unsigned bBase = sb + oBh + (unsigned)s * BSTG;
#pragma unroll
        for (int h = 0; h < 2; ++h) {
            unsigned ah[4][4], al[4][4], bh[4][2], bl[4][2];
#pragma unroll
            for (int mt = 0; mt < 4; ++mt) {
                unsigned off = (unsigned)((wm * 64 + mt * 16 + r + sx * 8) * 80 + h * 32 + sy * 16);
                LDSM4(ah[mt][0], ah[mt][1], ah[mt][2], ah[mt][3], aBase + off);
                LDSM4(al[mt][0], al[mt][1], al[mt][2], al[mt][3], aBase + oAl + off);
            }
#pragma unroll
            for (int p = 0; p < 2; ++p) {
                unsigned t0, t1, t2, t3;
                if (BT) {
                    unsigned off = (unsigned)((h * 16 + r + sx * 8) * 272 + (wn * 32 + p * 16 + sy * 8) * 2);
                    LDSM4T(t0, t1, t2, t3, bBase + off);
                    bh[2*p][0] = t0; bh[2*p][1] = t1; bh[2*p+1][0] = t2; bh[2*p+1][1] = t3;
                    LDSM4T(t0, t1, t2, t3, bBase + 3u * 8704u + off);
                    bl[2*p][0] = t0; bl[2*p][1] = t1; bl[2*p+1][0] = t2; bl[2*p+1][1] = t3;
                } else {
                    unsigned off = (unsigned)((wn * 32 + p * 16 + r + sy * 8) * 80 + h * 32 + sx * 16);
                    LDSM4(t0, t1, t2, t3, bBase + off);
                    bh[2*p][0] = t0; bh[2*p][1] = t1; bh[2*p+1][0] = t2; bh[2*p+1][1] = t3;
                    LDSM4(t0, t1, t2, t3, bBase + 3u * 10240u + off);
                    bl[2*p][0] = t0; bl[2*p][1] = t1; bl[2*p+1][0] = t2; bl[2*p+1][1] = t3;
                }
            }
#pragma unroll
            for (int mt = 0; mt < 4; ++mt)
#pragma unroll
                for (int nt = 0; nt < 4; ++nt) {
                    MMA(acc[mt][nt], ah[mt], bh[nt]);
                    MMA(acc[mt][nt], ah[mt], bl[nt]);
                    MMA(acc[mt][nt], al[mt], bh[nt]);
                }
        }
        __syncthreads();
    }
}

// ---------------- prep: fp32 -> bf16 hi/lo ----------------
__global__ void k_cvt(const float4* __restrict__ src, __nv_bfloat162* __restrict__ dh,
                      __nv_bfloat162* __restrict__ dl, int n4) {
    int i = blockIdx.x * blockDim.x + threadIdx.x;
    if (i >= n4) return;
    float4 v = src[i];
    __nv_bfloat162 h0, l0, h1, l1;
    split2(v.x, v.y, h0, l0);
    split2(v.z, v.w, h1, l1);
    dh[2 * i] = h0; dh[2 * i + 1] = h1;
    dl[2 * i] = l0; dl[2 * i + 1] = l1;
}

// ---------------- K0: A_k = U^T diag(S_k^2) U (fp32 SIMT, small) ----------------
__device__ __forceinline__ void mm_tile(const float As[16][68], const float Bs[16][68],
                                        float acc[4][4], int tx, int ty) {
#pragma unroll
    for (int kk = 0; kk < 16; ++kk) {
        float4 a4 = *(const float4*)&As[kk][ty << 2];
        float4 b4 = *(const float4*)&Bs[kk][tx << 2];
        float a[4] = {a4.x, a4.y, a4.z, a4.w};
        float b[4] = {b4.x, b4.y, b4.z, b4.w};
#pragma unroll
        for (int i = 0; i < 4; ++i)
#pragma unroll
            for (int j = 0; j < 4; ++j)
                acc[i][j] = fmaf(a[i], b[j], acc[i][j]);
    }
}

__global__ void k_buildA(const float* __restrict__ U, const float* __restrict__ S1,
                         const float* __restrict__ S2) {
    int kz = blockIdx.z;
    const float* S = kz ? S2 : S1;
    int j0 = blockIdx.y << 6, i0 = blockIdx.x << 6;
    __shared__ float As[16][68], Bs[16][68];
    int tid = threadIdx.x, tx = tid & 15, ty = tid >> 4;
    float acc[4][4] = {};
    for (int t0 = 0; t0 < DD; t0 += 16) {
        {
            int kk = tid >> 4, c = (tid & 15) << 2;
            int t = t0 + kk;
            float s = S[t]; float s2 = s * s;
            float4 a = *(const float4*)(U + (size_t)t * DD + j0 + c);
            a.x *= s2; a.y *= s2; a.z *= s2; a.w *= s2;
            *(float4*)&As[kk][c] = a;
            *(float4*)&Bs[kk][c] = *(const float4*)(U + (size_t)t * DD + i0 + c);
        }
        __syncthreads();
        mm_tile(As, Bs, acc, tx, ty);
        __syncthreads();
    }
    __nv_bfloat16* Ch = g_Ah[kz];
    __nv_bfloat16* Cl = g_Al[kz];
#pragma unroll
    for (int i = 0; i < 4; ++i) {
        int row = j0 + (ty << 2) + i, col = i0 + (tx << 2);
        __nv_bfloat162 h0, l0, h1, l1;
        split2(acc[i][0], acc[i][1], h0, l0);
        split2(acc[i][2], acc[i][3], h1, l1);
        size_t idx = (size_t)row * DD + col;
        *(__nv_bfloat162*)(Ch + idx)     = h0;
        *(__nv_bfloat162*)(Ch + idx + 2) = h1;
        *(__nv_bfloat162*)(Cl + idx)     = l0;
        *(__nv_bfloat162*)(Cl + idx + 2) = l1;
    }
}

// ---------------- K1: x_k = x @ A_k (tensor, NN) ----------------
__global__ void __launch_bounds__(256, 1) k_xk() {
    int z = blockIdx.z;
    int row0 = blockIdx.y << 7, col0 = blockIdx.x << 7;
    float acc[4][4][4] = {};
    gemm_main<true>(g_xh, g_xl, DD, g_Ah[z], g_Al[z], DD, DD, row0, col0, acc);
    int lane = threadIdx.x & 31, wid = threadIdx.x >> 5;
    int wm = wid & 1, wn = wid >> 1, g = lane >> 2, tg = lane & 3;
    __nv_bfloat16* Ch = g_xkh[z];
    __nv_bfloat16* Cl = g_xkl[z];
#pragma unroll
    for (int mt = 0; mt < 4; ++mt)
#pragma unroll
        for (int nt = 0; nt < 4; ++nt) {
            int row = row0 + wm * 64 + mt * 16 + g;
            int col = col0 + wn * 32 + nt * 8 + tg * 2;
#pragma unroll
            for (int hh = 0; hh < 2; ++hh) {
                __nv_bfloat162 hi, lo;
                split2(acc[mt][nt][2 * hh], acc[mt][nt][2 * hh + 1], hi, lo);
                size_t idx = (size_t)(row + hh * 8) * DD + col;
                *(__nv_bfloat162*)(Ch + idx) = hi;
                *(__nv_bfloat162*)(Cl + idx) = lo;
            }
        }
}

// ---------------- K2: pos softmax ----------------
__global__ void k_pos(const float* __restrict__ coords, const float* __restrict__ pe) {
    int n = blockIdx.x;
    int tid = threadIdx.x;
    __shared__ float red[16];
    float p[6];
#pragma unroll
    for (int c = 0; c < 6; ++c) p[c] = pe[n * 6 + c];
    float v[4];
#pragma unroll
    for (int i = 0; i < 4; ++i) {
        int m = tid + (i << 8);
        const float* cr = coords + ((size_t)n * MKV + m) * 6;
        v[i] = cr[0]*p[0] + cr[1]*p[1] + cr[2]*p[2] + cr[3]*p[3] + cr[4]*p[4] + cr[5]*p[5];
    }
    float mx = fmaxf(fmaxf(v[0], v[1]), fmaxf(v[2], v[3]));
#pragma unroll
    for (int o = 16; o; o >>= 1) mx = fmaxf(mx, __shfl_xor_sync(0xffffffffu, mx, o));
    int w = tid >> 5, lane = tid & 31;
    if (lane == 0) red[w] = mx;
    __syncthreads();
    mx = red[0];
#pragma unroll
    for (int i = 1; i < 8; ++i) mx = fmaxf(mx, red[i]);
    __syncthreads();
    float e = 0.f;
#pragma unroll
    for (int i = 0; i < 4; ++i) { v[i] = __expf(v[i] - mx); e += v[i]; }
#pragma unroll
    for (int o = 16; o; o >>= 1) e += __shfl_xor_sync(0xffffffffu, e, o);
    if (lane == 0) red[w] = e;
    __syncthreads();
    e = 0.f;
#pragma unroll
    for (int i = 0; i < 8; ++i) e += red[i];
    float rinv = __frcp_rn(e);
#pragma unroll
    for (int i = 0; i < 4; ++i) {
        int m = tid + (i << 8);
        g_pos[(size_t)n * MKV + m] = v[i] * rinv;
    }
}

// ---------------- K3: scores (tensor, NT) ----------------
__global__ void __launch_bounds__(256, 1) k_scores() {
    int z = blockIdx.z; int b = z >> 1; int k2 = z & 1;
    int row0 = blockIdx.y << 7, col0 = blockIdx.x << 7;
    float acc[4][4][4] = {};
    const __nv_bfloat16* Ah = g_xkh[k2] + (size_t)b * NQ * DD;
    const __nv_bfloat16* Al = g_xkl[k2] + (size_t)b * NQ * DD;
    const __nv_bfloat16* Bh = g_yh + (size_t)b * MKV * DD;
    const __nv_bfloat16* Bl = g_yl + (size_t)b * MKV * DD;
    gemm_main<false>(Ah, Al, DD, Bh, Bl, DD, DD, row0, col0, acc);
    int lane = threadIdx.x & 31, wid = threadIdx.x >> 5;
    int wm = wid & 1, wn = wid >> 1, g = lane >> 2, tg = lane & 3;
    float* C = g_s + ((size_t)z * NQ) * MKV;
#pragma unroll
    for (int mt = 0; mt < 4; ++mt)
#pragma unroll
        for (int nt = 0; nt < 4; ++nt) {
            int row = row0 + wm * 64 + mt * 16 + g;
            int col = col0 + wn * 32 + nt * 8 + tg * 2;
#pragma unroll
            for (int hh = 0; hh < 2; ++hh) {
                float2 v = make_float2(acc[mt][nt][2 * hh] * SCALE, acc[mt][nt][2 * hh + 1] * SCALE);
                *(float2*)(C + (size_t)(row + hh * 8) * MKV + col) = v;
            }
        }
}

// ---------------- K4: softmax + mix + entropy + route ----------------
__device__ __forceinline__ void blockReduce2(float& a, float& b, bool domax, float* red) {
#pragma unroll
    for (int o = 16; o; o >>= 1) {
        float ta = __shfl_xor_sync(0xffffffffu, a, o);
        float tb = __shfl_xor_sync(0xffffffffu, b, o);
        if (domax) { a = fmaxf(a, ta); b = fmaxf(b, tb); }
        else       { a += ta;          b += tb; }
    }
    int w = threadIdx.x >> 5, lane = threadIdx.x & 31;
    __syncthreads();
    if (lane == 0) { red[w] = a; red[8 + w] = b; }
    __syncthreads();
    a = red[0]; b = red[8];
#pragma unroll
    for (int i = 1; i < 8; ++i) {
        if (domax) { a = fmaxf(a, red[i]); b = fmaxf(b, red[8 + i]); }
        else       { a += red[i];          b += red[8 + i]; }
    }
}

__global__ void k_route(const float* __restrict__ gate, const float* __restrict__ temp,
                        float* __restrict__ heat_out) {
    int n = blockIdx.x, b = blockIdx.y;
    int tid = threadIdx.x;
    __shared__ float red[16];
    const float* s1 = g_s + ((size_t)(b * 2 + 0) * NQ + n) * MKV;
    const float* s2 = g_s + ((size_t)(b * 2 + 1) * NQ + n) * MKV;
    const float* pp = g_pos + (size_t)n * MKV;
    int base = tid * 4;
    float4 V1 = *(const float4*)(s1 + base);
    float4 V2 = *(const float4*)(s2 + base);
    float4 PV = *(const float4*)(pp + base);
    float v1[4] = {V1.x, V1.y, V1.z, V1.w};
    float v2[4] = {V2.x, V2.y, V2.z, V2.w};
    float pv[4] = {PV.x, PV.y, PV.z, PV.w};
    float m1 = -1e30f, m2 = -1e30f;
#pragma unroll
    for (int i = 0; i < 4; ++i) { m1 = fmaxf(m1, v1[i]); m2 = fmaxf(m2, v2[i]); }
    blockReduce2(m1, m2, true, red);
    float e1 = 0.f, e2 = 0.f;
#pragma unroll
    for (int i = 0; i < 4; ++i) {
        v1[i] = __expf(v1[i] - m1); e1 += v1[i];
        v2[i] = __expf(v2[i] - m2); e2 += v2[i];
    }
    blockReduce2(e1, e2, false, red);
    float r1 = __frcp_rn(e1), r2 = __frcp_rn(e2);
    float gg = gate[0];
    float gsig = 1.f / (1.f + __expf(-gg));
    float og = 1.f - gsig;
    float ent1 = 0.f, ent2 = 0.f;
#pragma unroll
    for (int i = 0; i < 4; ++i) {
        float a1 = og * v1[i] * r1 + gsig * pv[i];
        float a2 = og * v2[i] * r2 + gsig * pv[i];
        v1[i] = a1; v2[i] = a2;
        ent1 -= a1 * __logf(a1 + 1e-8f);
        ent2 -= a2 * __logf(a2 + 1e-8f);
    }
    blockReduce2(ent1, ent2, false, red);
    float tt = temp[0];
    float h1 = 2.f - 2.f / (1.f + __expf(-tt * ent1));
    float h2 = 2.f - 2.f / (1.f + __expf(-tt * ent2));
    bool fg = (h1 >= h2);
    if (tid == 0) heat_out[(size_t)b * NQ + n] = fg ? h1 : h2;
    size_t rowoff = ((size_t)b * NQ + n) * MKV;
    __nv_bfloat162 h01, l01, h23, l23;
    float a0 = fg ? v1[0] : v2[0], a1 = fg ? v1[1] : v2[1];
    float a2 = fg ? v1[2] : v2[2], a3 = fg ? v1[3] : v2[3];
    split2(a0, a1, h01, l01);
    split2(a2, a3, h23, l23);
    *(__nv_bfloat162*)(g_ach + rowoff + base)     = h01;
    *(__nv_bfloat162*)(g_ach + rowoff + base + 2) = h23;
    *(__nv_bfloat162*)(g_acl + rowoff + base)     = l01;
    *(__nv_bfloat162*)(g_acl + rowoff + base + 2) = l23;
}

// ---------------- K5: out = attn_c @ y (tensor, NN) ----------------
__global__ void __launch_bounds__(256, 1) k_av(float* __restrict__ out) {
    int b = blockIdx.z;
    int row0 = blockIdx.y << 7, col0 = blockIdx.x << 7;
    float acc[4][4][4] = {};
    const __nv_bfloat16* Ah = g_ach + (size_t)b * NQ * MKV;
    const __nv_bfloat16* Al = g_acl + (size_t)b * NQ * MKV;
    const __nv_bfloat16* Bh = g_yh + (size_t)b * MKV * DD;
    const __nv_bfloat16* Bl = g_yl + (size_t)b * MKV * DD;
    gemm_main<true>(Ah, Al, MKV, Bh, Bl, DD, MKV, row0, col0, acc);
    int lane = threadIdx.x & 31, wid = threadIdx.x >> 5;
    int wm = wid & 1, wn = wid >> 1, g = lane >> 2, tg = lane & 3;
    float* C = out + (size_t)b * NQ * DD;
#pragma unroll
    for (int mt = 0; mt < 4; ++mt)
#pragma unroll
        for (int nt = 0; nt < 4; ++nt) {
            int row = row0 + wm * 64 + mt * 16 + g;
            int col = col0 + wn * 32 + nt * 8 + tg * 2;
#pragma unroll
            for (int hh = 0; hh < 2; ++hh) {
                float2 v = make_float2(acc[mt][nt][2 * hh], acc[mt][nt][2 * hh + 1]);
                *(float2*)(C + (size_t)(row + hh * 8) * DD + col) = v;
            }
        }
}

// ---------------- launch ----------------
extern "C" void kernel_launch(void* const* d_in, const int* in_sizes, int n_in,
                              void* d_out, int out_size) {
    const float* x      = (const float*)d_in[0];
    const float* y      = (const float*)d_in[1];
    const float* coords = (const float*)d_in[2];
    const float* U      = (const float*)d_in[3];
    const float* S1     = (const float*)d_in[4];
    const float* S2     = (const float*)d_in[5];
    const float* gating = (const float*)d_in[6];
    const float* temp   = (const float*)d_in[7];
    const float* pe     = (const float*)d_in[8];
    float* out  = (float*)d_out;                 // [B,N,D]
    float* heat = out + (size_t)BB * NQ * DD;    // [B,N,1]

    cudaFuncSetAttribute(k_xk,     cudaFuncAttributeMaxDynamicSharedMemorySize, 113664);
    cudaFuncSetAttribute(k_scores, cudaFuncAttributeMaxDynamicSharedMemorySize, 122880);
    cudaFuncSetAttribute(k_av,     cudaFuncAttributeMaxDynamicSharedMemorySize, 113664);

    // device-global pointers for prep kernels
    __nv_bfloat16 *xh, *xl, *yh, *yl;
    cudaGetSymbolAddress((void**)&xh, g_xh);
    cudaGetSymbolAddress((void**)&xl, g_xl);
    cudaGetSymbolAddress((void**)&yh, g_yh);
    cudaGetSymbolAddress((void**)&yl, g_yl);

    int n4 = BB * NQ * DD / 4;
    k_cvt<<<(n4 + 255) / 256, 256>>>((const float4*)x, (__nv_bfloat162*)xh, (__nv_bfloat162*)xl, n4);
    k_cvt<<<(n4 + 255) / 256, 256>>>((const float4*)y, (__nv_bfloat162*)yh, (__nv_bfloat162*)yl, n4);
    k_buildA<<<dim3(DD / 64, DD / 64, 2), 256>>>(U, S1, S2);
    k_pos<<<dim3(NQ), 256>>>(coords, pe);
    k_xk<<<dim3(DD / 128, BB * NQ / 128, 2), 256, 113664>>>();
    k_scores<<<dim3(MKV / 128, NQ / 128, BB * 2), 256, 122880>>>();
    k_route<<<dim3(NQ, BB), 256>>>(gating, temp, heat);
    k_av<<<dim3(DD / 128, NQ / 128, BB), 256, 113664>>>(out);
}

// round 3
// speedup vs baseline: 5.5167x; 1.5153x over previous
#include <cuda_runtime.h>
#include <cuda_bf16.h>
#include <math.h>

#define BB   16
#define NQ   1024
#define MKV  1024
#define DD   768
#define SCALE 0.03608439182435161f   // 768^-0.5

// ---------------- scratch (device globals) ----------------
__device__ __nv_bfloat16 g_Ah[2][DD * DD], g_Al[2][DD * DD];
__device__ __nv_bfloat16 g_xh[BB * NQ * DD], g_xl[BB * NQ * DD];
__device__ __nv_bfloat16 g_yh[BB * MKV * DD], g_yl[BB * MKV * DD];
__device__ __nv_bfloat16 g_xkh[2][BB * NQ * DD], g_xkl[2][BB * NQ * DD];
__device__ float g_pos[NQ * MKV];
__device__ float g_s[(size_t)BB * 2 * NQ * MKV];
__device__ __nv_bfloat16 g_ach[(size_t)BB * NQ * MKV], g_acl[(size_t)BB * NQ * MKV];
__device__ int g_same;   // 1 iff S1 == S2 exactly -> branch-2 work is redundant

// ---------------- PTX helpers ----------------
__device__ __forceinline__ unsigned u32smem(const void* p) {
    return (unsigned)__cvta_generic_to_shared(p);
}
#define CP16(dst, src) asm volatile("cp.async.cg.shared.global [%0], [%1], 16;\n" :: "r"(dst), "l"(src))
#define CPCOMMIT() asm volatile("cp.async.commit_group;\n" ::: "memory")
#define CPWAIT2() asm volatile("cp.async.wait_group 2;\n" ::: "memory")
#define LDSM4(R0,R1,R2,R3,addr) \
    asm volatile("ldmatrix.sync.aligned.m8n8.x4.shared.b16 {%0,%1,%2,%3}, [%4];" \
                 : "=r"(R0),"=r"(R1),"=r"(R2),"=r"(R3) : "r"(addr))
#define LDSM4T(R0,R1,R2,R3,addr) \
    asm volatile("ldmatrix.sync.aligned.m8n8.x4.trans.shared.b16 {%0,%1,%2,%3}, [%4];" \
                 : "=r"(R0),"=r"(R1),"=r"(R2),"=r"(R3) : "r"(addr))
#define MMA(C,A,B) \
    asm volatile("mma.sync.aligned.m16n8k16.row.col.f32.bf16.bf16.f32 " \
                 "{%0,%1,%2,%3},{%4,%5,%6,%7},{%8,%9},{%0,%1,%2,%3};" \
                 : "+f"((C)[0]),"+f"((C)[1]),"+f"((C)[2]),"+f"((C)[3]) \
                 : "r"((A)[0]),"r"((A)[1]),"r"((A)[2]),"r"((A)[3]),"r"((B)[0]),"r"((B)[1]))

__device__ __forceinline__ void split2(float a, float b, __nv_bfloat162& hi, __nv_bfloat162& lo) {
    __nv_bfloat16 h0 = __float2bfloat16(a), h1 = __float2bfloat16(b);
    __nv_bfloat16 l0 = __float2bfloat16(a - __bfloat162float(h0));
    __nv_bfloat16 l1 = __float2bfloat16(b - __bfloat162float(h1));
    hi.x = h0; hi.y = h1; lo.x = l0; lo.y = l1;
}

// ---------------- flag: S1 == S2 ? ----------------
__global__ void k_flag(const float* __restrict__ S1, const float* __restrict__ S2) {
    __shared__ int ok;
    if (threadIdx.x == 0) ok = 1;
    __syncthreads();
    for (int i = threadIdx.x; i < DD; i += blockDim.x)
        if (S1[i] != S2[i]) atomicAnd(&ok, 0);
    __syncthreads();
    if (threadIdx.x == 0) g_same = ok;
}

// ---------------- bf16-split GEMM mainloop ----------------
template<bool BT>
__device__ __forceinline__ void gemm_main(
    const __nv_bfloat16* __restrict__ Ah, const __nv_bfloat16* __restrict__ Al, int lda,
    const __nv_bfloat16* __restrict__ Bh, const __nv_bfloat16* __restrict__ Bl, int ldb,
    int K, int row0, int col0, float acc[4][4][4])
{
    extern __shared__ char smc[];
    const unsigned BSTG = BT ? 8704u : 10240u;
    const unsigned oAl = 30720u;
    const unsigned oBh = 61440u;
    unsigned sb = u32smem(smc);
    int tid = threadIdx.x;
    int KT = K >> 5;

    auto load_stage = [&](int s, int kt) {
        if (kt < KT) {
            int k0 = kt << 5;
#pragma unroll
            for (int i = 0; i < 2; ++i) {
                int c = tid * 2 + i, rr = c >> 2, ch = c & 3;
                size_t go = (size_t)(row0 + rr) * lda + k0 + ch * 8;
                unsigned d = sb + (unsigned)(s * 10240 + rr * 80 + ch * 16);
                CP16(d, Ah + go);
                CP16(d + oAl, Al + go);
            }
#pragma unroll
            for (int i = 0; i < 2; ++i) {
                int c = tid * 2 + i;
                if (BT) {
                    int kr = c >> 4, ch = c & 15;
                    size_t go = (size_t)(k0 + kr) * ldb + col0 + ch * 8;
                    unsigned d = sb + oBh + (unsigned)(s * 8704 + kr * 272 + ch * 16);
                    CP16(d, Bh + go);
                    CP16(d + 3u * 8704u, Bl + go);
                } else {
                    int rr = c >> 2, ch = c & 3;
                    size_t go = (size_t)(col0 + rr) * ldb + k0 + ch * 8;
                    unsigned d = sb + oBh + (unsigned)(s * 10240 + rr * 80 + ch * 16);
                    CP16(d, Bh + go);
                    CP16(d + 3u * 10240u, Bl + go);
                }
            }
        }
        CPCOMMIT();
    };

    load_stage(0, 0);
    load_stage(1, 1);

    int lane = tid & 31, wid = tid >> 5;
    int wm = wid & 1, wn = wid >> 1;
    int r = lane & 7, sel = lane >> 3, sx = sel & 1, sy = sel >> 1;

    for (int kt = 0; kt < KT; ++kt) {
        load_stage((kt + 2) % 3, kt + 2);
        CPWAIT2();
        __syncthreads();
        int s = kt % 3;
        unsigned aBase = sb + (unsigned)(s * 10240);
        unsigned bBase = sb + oBh + (unsigned)s * BSTG;
#pragma unroll
        for (int h = 0; h < 2; ++h) {
            unsigned ah[4][4], al[4][4], bh[4][2], bl[4][2];
#pragma unroll
            for (int mt = 0; mt < 4; ++mt) {
                unsigned off = (unsigned)((wm * 64 + mt * 16 + r + sx * 8) * 80 + h * 32 + sy * 16);
                LDSM4(ah[mt][0], ah[mt][1], ah[mt][2], ah[mt][3], aBase + off);
                LDSM4(al[mt][0], al[mt][1], al[mt][2], al[mt][3], aBase + oAl + off);
            }
#pragma unroll
            for (int p = 0; p < 2; ++p) {
                unsigned t0, t1, t2, t3;
                if (BT) {
                    unsigned off = (unsigned)((h * 16 + r + sx * 8) * 272 + (wn * 32 + p * 16 + sy * 8) * 2);
                    LDSM4T(t0, t1, t2, t3, bBase + off);
                    bh[2*p][0] = t0; bh[2*p][1] = t1; bh[2*p+1][0] = t2; bh[2*p+1][1] = t3;
                    LDSM4T(t0, t1, t2, t3, bBase + 3u * 8704u + off);
                    bl[2*p][0] = t0; bl[2*p][1] = t1; bl[2*p+1][0] = t2; bl[2*p+1][1] = t3;
                } else {
                    unsigned off = (unsigned)((wn * 32 + p * 16 + r + sy * 8) * 80 + h * 32 + sx * 16);
                    LDSM4(t0, t1, t2, t3, bBase + off);
                    bh[2*p][0] = t0; bh[2*p][1] = t1; bh[2*p+1][0] = t2; bh[2*p+1][1] = t3;
                    LDSM4(t0, t1, t2, t3, bBase + 3u * 10240u + off);
                    bl[2*p][0] = t0; bl[2*p][1] = t1; bl[2*p+1][0] = t2; bl[2*p+1][1] = t3;
                }
            }
#pragma unroll
            for (int mt = 0; mt < 4; ++mt)
#pragma unroll
                for (int nt = 0; nt < 4; ++nt) {
                    MMA(acc[mt][nt], ah[mt], bh[nt]);
                    MMA(acc[mt][nt], ah[mt], bl[nt]);
                    MMA(acc[mt][nt], al[mt], bh[nt]);
                }
        }
        __syncthreads();
    }
}

// ---------------- prep: fp32 -> bf16 hi/lo ----------------
__global__ void k_cvt(const float4* __restrict__ src, __nv_bfloat162* __restrict__ dh,
                      __nv_bfloat162* __restrict__ dl, int n4) {
    int i = blockIdx.x * blockDim.x + threadIdx.x;
    if (i >= n4) return;
    float4 v = src[i];
    __nv_bfloat162 h0, l0, h1, l1;
    split2(v.x, v.y, h0, l0);
    split2(v.z, v.w, h1, l1);
    dh[2 * i] = h0; dh[2 * i + 1] = h1;
    dl[2 * i] = l0; dl[2 * i + 1] = l1;
}

// ---------------- K0: A_k = U^T diag(S_k^2) U ----------------
__device__ __forceinline__ void mm_tile(const float As[16][68], const float Bs[16][68],
                                        float acc[4][4], int tx, int ty) {
#pragma unroll
    for (int kk = 0; kk < 16; ++kk) {
        float4 a4 = *(const float4*)&As[kk][ty << 2];
        float4 b4 = *(const float4*)&Bs[kk][tx << 2];
        float a[4] = {a4.x, a4.y, a4.z, a4.w};
        float b[4] = {b4.x, b4.y, b4.z, b4.w};
#pragma unroll
        for (int i = 0; i < 4; ++i)
#pragma unroll
            for (int j = 0; j < 4; ++j)
                acc[i][j] = fmaf(a[i], b[j], acc[i][j]);
    }
}

__global__ void k_buildA(const float* __restrict__ U, const float* __restrict__ S1,
                         const float* __restrict__ S2) {
    int kz = blockIdx.z;
    if (kz == 1 && g_same) return;
    const float* S = kz ? S2 : S1;
    int j0 = blockIdx.y << 6, i0 = blockIdx.x << 6;
    __shared__ float As[16][68], Bs[16][68];
    int tid = threadIdx.x, tx = tid & 15, ty = tid >> 4;
    float acc[4][4] = {};
    for (int t0 = 0; t0 < DD; t0 += 16) {
        {
            int kk = tid >> 4, c = (tid & 15) << 2;
            int t = t0 + kk;
            float s = S[t]; float s2 = s * s;
            float4 a = *(const float4*)(U + (size_t)t * DD + j0 + c);
            a.x *= s2; a.y *= s2; a.z *= s2; a.w *= s2;
            *(float4*)&As[kk][c] = a;
            *(float4*)&Bs[kk][c] = *(const float4*)(U + (size_t)t * DD + i0 + c);
        }
        __syncthreads();
        mm_tile(As, Bs, acc, tx, ty);
        __syncthreads();
    }
    __nv_bfloat16* Ch = g_Ah[kz];
    __nv_bfloat16* Cl = g_Al[kz];
#pragma unroll
    for (int i = 0; i < 4; ++i) {
        int row = j0 + (ty << 2) + i, col = i0 + (tx << 2);
        __nv_bfloat162 h0, l0, h1, l1;
        split2(acc[i][0], acc[i][1], h0, l0);
        split2(acc[i][2], acc[i][3], h1, l1);
        size_t idx = (size_t)row * DD + col;
        *(__nv_bfloat162*)(Ch + idx)     = h0;
        *(__nv_bfloat162*)(Ch + idx + 2) = h1;
        *(__nv_bfloat162*)(Cl + idx)     = l0;
        *(__nv_bfloat162*)(Cl + idx + 2) = l1;
    }
}

// ---------------- K1: x_k = x @ A_k ----------------
__global__ void __launch_bounds__(256, 1) k_xk() {
    int z = blockIdx.z;
    if (z == 1 && g_same) return;
    int row0 = blockIdx.y << 7, col0 = blockIdx.x << 7;
    float acc[4][4][4] = {};
    gemm_main<true>(g_xh, g_xl, DD, g_Ah[z], g_Al[z], DD, DD, row0, col0, acc);
    int lane = threadIdx.x & 31, wid = threadIdx.x >> 5;
    int wm = wid & 1, wn = wid >> 1, g = lane >> 2, tg = lane & 3;
    __nv_bfloat16* Ch = g_xkh[z];
    __nv_bfloat16* Cl = g_xkl[z];
#pragma unroll
    for (int mt = 0; mt < 4; ++mt)
#pragma unroll
        for (int nt = 0; nt < 4; ++nt) {
            int row = row0 + wm * 64 + mt * 16 + g;
            int col = col0 + wn * 32 + nt * 8 + tg * 2;
#pragma unroll
            for (int hh = 0; hh < 2; ++hh) {
                __nv_bfloat162 hi, lo;
                split2(acc[mt][nt][2 * hh], acc[mt][nt][2 * hh + 1], hi, lo);
                size_t idx = (size_t)(row + hh * 8) * DD + col;
                *(__nv_bfloat162*)(Ch + idx) = hi;
                *(__nv_bfloat162*)(Cl + idx) = lo;
            }
        }
}

// ---------------- K2: pos softmax ----------------
__global__ void k_pos(const float* __restrict__ coords, const float* __restrict__ pe) {
    int n = blockIdx.x;
    int tid = threadIdx.x;
    __shared__ float red[16];
    float p[6];
#pragma unroll
    for (int c = 0; c < 6; ++c) p[c] = pe[n * 6 + c];
    float v[4];
#pragma unroll
    for (int i = 0; i < 4; ++i) {
        int m = tid + (i << 8);
        const float* cr = coords + ((size_t)n * MKV + m) * 6;
        v[i] = cr[0]*p[0] + cr[1]*p[1] + cr[2]*p[2] + cr[3]*p[3] + cr[4]*p[4] + cr[5]*p[5];
    }
    float mx = fmaxf(fmaxf(v[0], v[1]), fmaxf(v[2], v[3]));
#pragma unroll
    for (int o = 16; o; o >>= 1) mx = fmaxf(mx, __shfl_xor_sync(0xffffffffu, mx, o));
    int w = tid >> 5, lane = tid & 31;
    if (lane == 0) red[w] = mx;
    __syncthreads();
    mx = red[0];
#pragma unroll
    for (int i = 1; i < 8; ++i) mx = fmaxf(mx, red[i]);
    __syncthreads();
    float e = 0.f;
#pragma unroll
    for (int i = 0; i < 4; ++i) { v[i] = __expf(v[i] - mx); e += v[i]; }
#pragma unroll
    for (int o = 16; o; o >>= 1) e += __shfl_xor_sync(0xffffffffu, e, o);
    if (lane == 0) red[w] = e;
    __syncthreads();
    e = 0.f;
#pragma unroll
    for (int i = 0; i < 8; ++i) e += red[i];
    float rinv = __frcp_rn(e);
#pragma unroll
    for (int i = 0; i < 4; ++i) {
        int m = tid + (i << 8);
        g_pos[(size_t)n * MKV + m] = v[i] * rinv;
    }
}

// ---------------- K3: scores ----------------
__global__ void __launch_bounds__(256, 1) k_scores() {
    int z = blockIdx.z; int b = z >> 1; int k2 = z & 1;
    if (k2 == 1 && g_same) return;
    int row0 = blockIdx.y << 7, col0 = blockIdx.x << 7;
    float acc[4][4][4] = {};
    const __nv_bfloat16* Ah = g_xkh[k2] + (size_t)b * NQ * DD;
    const __nv_bfloat16* Al = g_xkl[k2] + (size_t)b * NQ * DD;
    const __nv_bfloat16* Bh = g_yh + (size_t)b * MKV * DD;
    const __nv_bfloat16* Bl = g_yl + (size_t)b * MKV * DD;
    gemm_main<false>(Ah, Al, DD, Bh, Bl, DD, DD, row0, col0, acc);
    int lane = threadIdx.x & 31, wid = threadIdx.x >> 5;
    int wm = wid & 1, wn = wid >> 1, g = lane >> 2, tg = lane & 3;
    float* C = g_s + ((size_t)z * NQ) * MKV;
#pragma unroll
    for (int mt = 0; mt < 4; ++mt)
#pragma unroll
        for (int nt = 0; nt < 4; ++nt) {
            int row = row0 + wm * 64 + mt * 16 + g;
            int col = col0 + wn * 32 + nt * 8 + tg * 2;
#pragma unroll
            for (int hh = 0; hh < 2; ++hh) {
                float2 v = make_float2(acc[mt][nt][2 * hh] * SCALE, acc[mt][nt][2 * hh + 1] * SCALE);
                *(float2*)(C + (size_t)(row + hh * 8) * MKV + col) = v;
            }
        }
}

// ---------------- K4: softmax + mix + entropy + route ----------------
__device__ __forceinline__ void blockReduce2(float& a, float& b, bool domax, float* red) {
#pragma unroll
    for (int o = 16; o; o >>= 1) {
        float ta = __shfl_xor_sync(0xffffffffu, a, o);
        float tb = __shfl_xor_sync(0xffffffffu, b, o);
        if (domax) { a = fmaxf(a, ta); b = fmaxf(b, tb); }
        else       { a += ta;          b += tb; }
    }
    int w = threadIdx.x >> 5, lane = threadIdx.x & 31;
    __syncthreads();
    if (lane == 0) { red[w] = a; red[8 + w] = b; }
    __syncthreads();
    a = red[0]; b = red[8];
#pragma unroll
    for (int i = 1; i < 8; ++i) {
        if (domax) { a = fmaxf(a, red[i]); b = fmaxf(b, red[8 + i]); }
        else       { a += red[i];          b += red[8 + i]; }
    }
}

__global__ void k_route(const float* __restrict__ gate, const float* __restrict__ temp,
                        float* __restrict__ heat_out) {
    int n = blockIdx.x, b = blockIdx.y;
    int tid = threadIdx.x;
    __shared__ float red[16];
    int same = g_same;
    const float* s1 = g_s + ((size_t)(b * 2 + 0) * NQ + n) * MKV;
    const float* s2 = g_s + ((size_t)(b * 2 + 1) * NQ + n) * MKV;
    const float* pp = g_pos + (size_t)n * MKV;
    int base = tid * 4;
    float4 V1 = *(const float4*)(s1 + base);
    float4 PV = *(const float4*)(pp + base);
    float v1[4] = {V1.x, V1.y, V1.z, V1.w};
    float pv[4] = {PV.x, PV.y, PV.z, PV.w};
    float gg = gate[0];
    float gsig = 1.f / (1.f + __expf(-gg));
    float og = 1.f - gsig;
    float tt = temp[0];
    size_t rowoff = ((size_t)b * NQ + n) * MKV;

    if (same) {
        // branches identical -> route picks index 0 (h1 >= h2 with equality)
        float m1 = -1e30f, dummy = -1e30f;
#pragma unroll
        for (int i = 0; i < 4; ++i) m1 = fmaxf(m1, v1[i]);
        blockReduce2(m1, dummy, true, red);
        float e1 = 0.f, d2 = 0.f;
#pragma unroll
        for (int i = 0; i < 4; ++i) { v1[i] = __expf(v1[i] - m1); e1 += v1[i]; }
        blockReduce2(e1, d2, false, red);
        float r1 = __frcp_rn(e1);
        float ent1 = 0.f, d3 = 0.f;
#pragma unroll
        for (int i = 0; i < 4; ++i) {
            float a1 = og * v1[i] * r1 + gsig * pv[i];
            v1[i] = a1;
            ent1 -= a1 * __logf(a1 + 1e-8f);
        }
        blockReduce2(ent1, d3, false, red);
        float h1 = 2.f - 2.f / (1.f + __expf(-tt * ent1));
        if (tid == 0) heat_out[(size_t)b * NQ + n] = h1;
        __nv_bfloat162 h01, l01, h23, l23;
        split2(v1[0], v1[1], h01, l01);
        split2(v1[2], v1[3], h23, l23);
        *(__nv_bfloat162*)(g_ach + rowoff + base)     = h01;
        *(__nv_bfloat162*)(g_ach + rowoff + base + 2) = h23;
        *(__nv_bfloat162*)(g_acl + rowoff + base)     = l01;
        *(__nv_bfloat162*)(g_acl + rowoff + base + 2) = l23;
        return;
    }

    float4 V2 = *(const float4*)(s2 + base);
    float v2[4] = {V2.x, V2.y, V2.z, V2.w};
    float m1 = -1e30f, m2 = -1e30f;
#pragma unroll
    for (int i = 0; i < 4; ++i) { m1 = fmaxf(m1, v1[i]); m2 = fmaxf(m2, v2[i]); }
    blockReduce2(m1, m2, true, red);
    float e1 = 0.f, e2 = 0.f;
#pragma unroll
    for (int i = 0; i < 4; ++i) {
        v1[i] = __expf(v1[i] - m1); e1 += v1[i];
        v2[i] = __expf(v2[i] - m2); e2 += v2[i];
    }
    blockReduce2(e1, e2, false, red);
    float r1 = __frcp_rn(e1), r2 = __frcp_rn(e2);
    float ent1 = 0.f, ent2 = 0.f;
#pragma unroll
    for (int i = 0; i < 4; ++i) {
        float a1 = og * v1[i] * r1 + gsig * pv[i];
        float a2 = og * v2[i] * r2 + gsig * pv[i];
        v1[i] = a1; v2[i] = a2;
        ent1 -= a1 * __logf(a1 + 1e-8f);
        ent2 -= a2 * __logf(a2 + 1e-8f);
    }
    blockReduce2(ent1, ent2, false, red);
    float h1 = 2.f - 2.f / (1.f + __expf(-tt * ent1));
    float h2 = 2.f - 2.f / (1.f + __expf(-tt * ent2));
    bool fg = (h1 >= h2);
    if (tid == 0) heat_out[(size_t)b * NQ + n] = fg ? h1 : h2;
    __nv_bfloat162 h01, l01, h23, l23;
    float a0 = fg ? v1[0] : v2[0], a1 = fg ? v1[1] : v2[1];
    float a2 = fg ? v1[2] : v2[2], a3 = fg ? v1[3] : v2[3];
    split2(a0, a1, h01, l01);
    split2(a2, a3, h23, l23);
    *(__nv_bfloat162*)(g_ach + rowoff + base)     = h01;
    *(__nv_bfloat162*)(g_ach + rowoff + base + 2) = h23;
    *(__nv_bfloat162*)(g_acl + rowoff + base)     = l01;
    *(__nv_bfloat162*)(g_acl + rowoff + base + 2) = l23;
}

// ---------------- K5: out = attn_c @ y ----------------
__global__ void __launch_bounds__(256, 1) k_av(float* __restrict__ out) {
    int b = blockIdx.z;
    int row0 = blockIdx.y << 7, col0 = blockIdx.x << 7;
    float acc[4][4][4] = {};
    const __nv_bfloat16* Ah = g_ach + (size_t)b * NQ * MKV;
    const __nv_bfloat16* Al = g_acl + (size_t)b * NQ * MKV;
    const __nv_bfloat16* Bh = g_yh + (size_t)b * MKV * DD;
    const __nv_bfloat16* Bl = g_yl + (size_t)b * MKV * DD;
    gemm_main<true>(Ah, Al, MKV, Bh, Bl, DD, MKV, row0, col0, acc);
    int lane = threadIdx.x & 31, wid = threadIdx.x >> 5;
    int wm = wid & 1, wn = wid >> 1, g = lane >> 2, tg = lane & 3;
    float* C = out + (size_t)b * NQ * DD;
#pragma unroll
    for (int mt = 0; mt < 4; ++mt)
#pragma unroll
        for (int nt = 0; nt < 4; ++nt) {
            int row = row0 + wm * 64 + mt * 16 + g;
            int col = col0 + wn * 32 + nt * 8 + tg * 2;
#pragma unroll
            for (int hh = 0; hh < 2; ++hh) {
                float2 v = make_float2(acc[mt][nt][2 * hh], acc[mt][nt][2 * hh + 1]);
                *(float2*)(C + (size_t)(row + hh * 8) * DD + col) = v;
            }
        }
}

// ---------------- launch ----------------
extern "C" void kernel_launch(void* const* d_in, const int* in_sizes, int n_in,
                              void* d_out, int out_size) {
    const float* x      = (const float*)d_in[0];
    const float* y      = (const float*)d_in[1];
    const float* coords = (const float*)d_in[2];
    const float* U      = (const float*)d_in[3];
    const float* S1     = (const float*)d_in[4];
    const float* S2     = (const float*)d_in[5];
    const float* gating = (const float*)d_in[6];
    const float* temp   = (const float*)d_in[7];
    const float* pe     = (const float*)d_in[8];
    float* out  = (float*)d_out;                 // [B,N,D]
    float* heat = out + (size_t)BB * NQ * DD;    // [B,N,1]

    cudaFuncSetAttribute(k_xk,     cudaFuncAttributeMaxDynamicSharedMemorySize, 113664);
    cudaFuncSetAttribute(k_scores, cudaFuncAttributeMaxDynamicSharedMemorySize, 122880);
    cudaFuncSetAttribute(k_av,     cudaFuncAttributeMaxDynamicSharedMemorySize, 113664);

    __nv_bfloat16 *xh, *xl, *yh, *yl;
    cudaGetSymbolAddress((void**)&xh, g_xh);
    cudaGetSymbolAddress((void**)&xl, g_xl);
    cudaGetSymbolAddress((void**)&yh, g_yh);
    cudaGetSymbolAddress((void**)&yl, g_yl);

    int n4 = BB * NQ * DD / 4;
    k_flag<<<1, 256>>>(S1, S2);
    k_cvt<<<(n4 + 255) / 256, 256>>>((const float4*)x, (__nv_bfloat162*)xh, (__nv_bfloat162*)xl, n4);
    k_cvt<<<(n4 + 255) / 256, 256>>>((const float4*)y, (__nv_bfloat162*)yh, (__nv_bfloat162*)yl, n4);
    k_buildA<<<dim3(DD / 64, DD / 64, 2), 256>>>(U, S1, S2);
    k_pos<<<dim3(NQ), 256>>>(coords, pe);
    k_xk<<<dim3(DD / 128, BB * NQ / 128, 2), 256, 113664>>>();
    k_scores<<<dim3(MKV / 128, NQ / 128, BB * 2), 256, 122880>>>();
    k_route<<<dim3(NQ, BB), 256>>>(gating, temp, heat);
    k_av<<<dim3(DD / 128, NQ / 128, BB), 256, 113664>>>(out);
}

// round 7
// speedup vs baseline: 5.8493x; 1.0603x over previous
#include <cuda_runtime.h>
#include <cuda_bf16.h>
#include <cstdint>
#include <cstddef>
#include <math.h>

#define BB   16
#define NQ   1024
#define MKV  1024
#define DD   768
#define SCALE 0.03608439182435161f   // 768^-0.5

// ---------------- scratch (device globals) ----------------
__device__ __nv_bfloat16 g_Ah[2][DD * DD], g_Al[2][DD * DD];        // A_k (symmetric)
__device__ __nv_bfloat16 g_UTh[DD * DD], g_UTl[DD * DD];            // U^T  [j][t]
__device__ __nv_bfloat16 g_UscTh[2][DD * DD], g_UscTl[2][DD * DD];  // (diag(S^2)U)^T [j][t]
__device__ __nv_bfloat16 g_xh[BB * NQ * DD], g_xl[BB * NQ * DD];
__device__ __nv_bfloat16 g_yh[BB * MKV * DD], g_yl[BB * MKV * DD];
__device__ __nv_bfloat16 g_xkh[2][BB * NQ * DD], g_xkl[2][BB * NQ * DD];
__device__ float g_pos[NQ * MKV];
__device__ float g_s[(size_t)BB * 2 * NQ * MKV];
__device__ __nv_bfloat16 g_ach[(size_t)BB * NQ * MKV], g_acl[(size_t)BB * NQ * MKV];
__device__ int g_same;   // 1 iff S1 == S2 exactly

// ---------------- PTX helpers ----------------
__device__ __forceinline__ unsigned u32smem(const void* p) {
    return (unsigned)__cvta_generic_to_shared(p);
}
#define CP16(dst, src) asm volatile("cp.async.cg.shared.global [%0], [%1], 16;\n" :: "r"(dst), "l"(src))
#define CPCOMMIT() asm volatile("cp.async.commit_group;\n" ::: "memory")
#define CPWAIT2() asm volatile("cp.async.wait_group 2;\n" ::: "memory")
#define LDSM4(R0,R1,R2,R3,addr) \
    asm volatile("ldmatrix.sync.aligned.m8n8.x4.shared.b16 {%0,%1,%2,%3}, [%4];" \
                 : "=r"(R0),"=r"(R1),"=r"(R2),"=r"(R3) : "r"(addr))
#define LDSM4T(R0,R1,R2,R3,addr) \
    asm volatile("ldmatrix.sync.aligned.m8n8.x4.trans.shared.b16 {%0,%1,%2,%3}, [%4];" \
                 : "=r"(R0),"=r"(R1),"=r"(R2),"=r"(R3) : "r"(addr))
#define MMA(C,A,B) \
    asm volatile("mma.sync.aligned.m16n8k16.row.col.f32.bf16.bf16.f32 " \
                 "{%0,%1,%2,%3},{%4,%5,%6,%7},{%8,%9},{%0,%1,%2,%3};" \
                 : "+f"((C)[0]),"+f"((C)[1]),"+f"((C)[2]),"+f"((C)[3]) \
                 : "r"((A)[0]),"r"((A)[1]),"r"((A)[2]),"r"((A)[3]),"r"((B)[0]),"r"((B)[1]))

__device__ __forceinline__ void split2(float a, float b, __nv_bfloat162& hi, __nv_bfloat162& lo) {
    __nv_bfloat16 h0 = __float2bfloat16(a), h1 = __float2bfloat16(b);
    __nv_bfloat16 l0 = __float2bfloat16(a - __bfloat162float(h0));
    __nv_bfloat16 l1 = __float2bfloat16(b - __bfloat162float(h1));
    hi.x = h0; hi.y = h1; lo.x = l0; lo.y = l1;
}

// ---------------- bf16-split HMMA GEMM mainloop (512 threads, 16 warps) ----------------
// Block tile 128x128, K-chunk 32, 3-stage cp.async pipeline.
// Warp grid 4M x 4N: each warp owns 32x32 (mt=2 x nt=4 of m16n8).
// A layout: [M][K] bf16 hi/lo. B: BT ? [K][N] (trans ldmatrix) : [N][K].

template<bool BT>
__device__ __forceinline__ void gemm_main(
    const __nv_bfloat16* __restrict__ Ah, const __nv_bfloat16* __restrict__ Al, int lda,
    const __nv_bfloat16* __restrict__ Bh, const __nv_bfloat16* __restrict__ Bl, int ldb,
    int K, int row0, int col0, float acc[2][4][4])
{
    extern __shared__ char smc[];
    const unsigned BSTG = BT ? 8704u : 10240u;
    const unsigned oAl = 30720u;
    const unsigned oBh = 61440u;
    unsigned sb = u32smem(smc);
    int tid = threadIdx.x;
    int KT = K >> 5;

    auto load_stage = [&](int s, int kt) {
        if (kt < KT) {
            int k0 = kt << 5;
            {   // A: 512 chunks of 16B for hi (and lo)
                int rr = tid >> 2, ch = tid & 3;
                size_t go = (size_t)(row0 + rr) * lda + k0 + ch * 8;
                unsigned d = sb + (unsigned)(s * 10240 + rr * 80 + ch * 16);
                CP16(d, Ah + go);
                CP16(d + oAl, Al + go);
            }
            if (BT) {
                int kr = tid >> 4, ch = tid & 15;
                size_t go = (size_t)(k0 + kr) * ldb + col0 + ch * 8;
                unsigned d = sb + oBh + (unsigned)(s * 8704 + kr * 272 + ch * 16);
                CP16(d, Bh + go);
                CP16(d + 3u * 8704u, Bl + go);
            } else {
                int rr = tid >> 2, ch = tid & 3;
                size_t go = (size_t)(col0 + rr) * ldb + k0 + ch * 8;
                unsigned d = sb + oBh + (unsigned)(s * 10240 + rr * 80 + ch * 16);
                CP16(d, Bh + go);
                CP16(d + 3u * 10240u, Bl + go);
            }
        }
        CPCOMMIT();
    };

    load_stage(0, 0);
    load_stage(1, 1);

    int lane = tid & 31, wid = tid >> 5;
    int wm = wid & 3, wn = wid >> 2;
    int r = lane & 7, sel = lane >> 3, sx = sel & 1, sy = sel >> 1;

    for (int kt = 0; kt < KT; ++kt) {
        load_stage((kt + 2) % 3, kt + 2);
        CPWAIT2();
        __syncthreads();
        int s = kt % 3;
        unsigned aBase = sb + (unsigned)(s * 10240);
        unsigned bBase = sb + oBh + (unsigned)s * BSTG;
#pragma unroll
        for (int h = 0; h < 2; ++h) {
            unsigned ah[2][4], al[2][4], bh[4][2], bl[4][2];
#pragma unroll
            for (int mt = 0; mt < 2; ++mt) {
                unsigned off = (unsigned)((wm * 32 + mt * 16 + r + sx * 8) * 80 + h * 32 + sy * 16);
                LDSM4(ah[mt][0], ah[mt][1], ah[mt][2], ah[mt][3], aBase + off);
                LDSM4(al[mt][0], al[mt][1], al[mt][2], al[mt][3], aBase + oAl + off);
            }
#pragma unroll
            for (int p = 0; p < 2; ++p) {
                unsigned t0, t1, t2, t3;
                if (BT) {
                    unsigned off = (unsigned)((h * 16 + r + sx * 8) * 272 + (wn * 32 + p * 16 + sy * 8) * 2);
                    LDSM4T(t0, t1, t2, t3, bBase + off);
                    bh[2*p][0] = t0; bh[2*p][1] = t1; bh[2*p+1][0] = t2; bh[2*p+1][1] = t3;
                    LDSM4T(t0, t1, t2, t3, bBase + 3u * 8704u + off);
                    bl[2*p][0] = t0; bl[2*p][1] = t1; bl[2*p+1][0] = t2; bl[2*p+1][1] = t3;
                } else {
                    unsigned off = (unsigned)((wn * 32 + p * 16 + r + sy * 8) * 80 + h * 32 + sx * 16);
                    LDSM4(t0, t1, t2, t3, bBase + off);
                    bh[2*p][0] = t0; bh[2*p][1] = t1; bh[2*p+1][0] = t2; bh[2*p+1][1] = t3;
                    LDSM4(t0, t1, t2, t3, bBase + 3u * 10240u + off);
                    bl[2*p][0] = t0; bl[2*p][1] = t1; bl[2*p+1][0] = t2; bl[2*p+1][1] = t3;
                }
            }
#pragma unroll
            for (int mt = 0; mt < 2; ++mt)
#pragma unroll
                for (int nt = 0; nt < 4; ++nt) {
                    MMA(acc[mt][nt], ah[mt], bh[nt]);
                    MMA(acc[mt][nt], ah[mt], bl[nt]);
                    MMA(acc[mt][nt], al[mt], bh[nt]);
                }
        }
        __syncthreads();
    }
}

// ---------------- small kernels ----------------
__global__ void k_flag(const float* __restrict__ S1, const float* __restrict__ S2) {
    __shared__ int ok;
    if (threadIdx.x == 0) ok = 1;
    __syncthreads();
    for (int i = threadIdx.x; i < DD; i += blockDim.x)
        if (S1[i] != S2[i]) atomicAnd(&ok, 0);
    __syncthreads();
    if (threadIdx.x == 0) g_same = ok;
}

__global__ void k_cvt(const float4* __restrict__ src, __nv_bfloat162* __restrict__ dh,
                      __nv_bfloat162* __restrict__ dl, int n4) {
    int i = blockIdx.x * blockDim.x + threadIdx.x;
    if (i >= n4) return;
    float4 v = src[i];
    __nv_bfloat162 h0, l0, h1, l1;
    split2(v.x, v.y, h0, l0);
    split2(v.z, v.w, h1, l1);
    dh[2 * i] = h0; dh[2 * i + 1] = h1;
    dl[2 * i] = l0; dl[2 * i + 1] = l1;
}

// transpose U -> UT (bf16 split) and (diag(S_k^2)U)^T
__global__ void k_prepU(const float* __restrict__ U, const float* __restrict__ S1,
                        const float* __restrict__ S2) {
    __shared__ float t[32][33];
    __shared__ float s2a[32], s2b[32];
    int j0 = blockIdx.x * 32, t0 = blockIdx.y * 32;
    int tx = threadIdx.x, ty = threadIdx.y;
    if (ty == 0) {
        float s = S1[t0 + tx]; s2a[tx] = s * s;
        float q = S2[t0 + tx]; s2b[tx] = q * q;
    }
#pragma unroll
    for (int r = 0; r < 4; ++r)
        t[ty * 4 + r][tx] = U[(size_t)(t0 + ty * 4 + r) * DD + j0 + tx];
    __syncthreads();
    int same = g_same;
#pragma unroll
    for (int r = 0; r < 4; ++r) {
        int jr = ty * 4 + r;
        float v = t[tx][jr];                       // U[t0+tx][j0+jr]
        size_t o = (size_t)(j0 + jr) * DD + t0 + tx;
        __nv_bfloat16 h = __float2bfloat16(v);
        g_UTh[o] = h;
        g_UTl[o] = __float2bfloat16(v - __bfloat162float(h));
        float va = v * s2a[tx];
        __nv_bfloat16 ha = __float2bfloat16(va);
        g_UscTh[0][o] = ha;
        g_UscTl[0][o] = __float2bfloat16(va - __bfloat162float(ha));
        if (!same) {
            float vb = v * s2b[tx];
            __nv_bfloat16 hb = __float2bfloat16(vb);
            g_UscTh[1][o] = hb;
            g_UscTl[1][o] = __float2bfloat16(vb - __bfloat162float(hb));
        }
    }
}

__global__ void k_pos(const float* __restrict__ coords, const float* __restrict__ pe) {
    int n = blockIdx.x;
    int tid = threadIdx.x;
    __shared__ float red[16];
    float p[6];
#pragma unroll
    for (int c = 0; c < 6; ++c) p[c] = pe[n * 6 + c];
    float v[4];
#pragma unroll
    for (int i = 0; i < 4; ++i) {
        int m = tid + (i << 8);
        const float* cr = coords + ((size_t)n * MKV + m) * 6;
        v[i] = cr[0]*p[0] + cr[1]*p[1] + cr[2]*p[2] + cr[3]*p[3] + cr[4]*p[4] + cr[5]*p[5];
    }
    float mx = fmaxf(fmaxf(v[0], v[1]), fmaxf(v[2], v[3]));
#pragma unroll
    for (int o = 16; o; o >>= 1) mx = fmaxf(mx, __shfl_xor_sync(0xffffffffu, mx, o));
    int w = tid >> 5, lane = tid & 31;
    if (lane == 0) red[w] = mx;
    __syncthreads();
    mx = red[0];
#pragma unroll
    for (int i = 1; i < 8; ++i) mx = fmaxf(mx, red[i]);
    __syncthreads();
    float e = 0.f;
#pragma unroll
    for (int i = 0; i < 4; ++i) { v[i] = __expf(v[i] - mx); e += v[i]; }
#pragma unroll
    for (int o = 16; o; o >>= 1) e += __shfl_xor_sync(0xffffffffu, e, o);
    if (lane == 0) red[w] = e;
    __syncthreads();
    e = 0.f;
#pragma unroll
    for (int i = 0; i < 8; ++i) e += red[i];
    float rinv = __frcp_rn(e);
#pragma unroll
    for (int i = 0; i < 4; ++i) {
        int m = tid + (i << 8);
        g_pos[(size_t)n * MKV + m] = v[i] * rinv;
    }
}

// ---------------- GEMM kernels (HMMA) ----------------

// A_k = UscT_k @ UT^T (NT, both [*][t] row-major), 768x768
__global__ void __launch_bounds__(512, 1) k_buildA() {
    int z = blockIdx.z;
    if (z == 1 && g_same) return;
    int row0 = blockIdx.y << 7, col0 = blockIdx.x << 7;
    float acc[2][4][4] = {};
    gemm_main<false>(g_UscTh[z], g_UscTl[z], DD,
                     g_UTh, g_UTl, DD,
                     DD, row0, col0, acc);
    int lane = threadIdx.x & 31, wid = threadIdx.x >> 5;
    int wm = wid & 3, wn = wid >> 2, g = lane >> 2, tg = lane & 3;
#pragma unroll
    for (int mt = 0; mt < 2; ++mt)
#pragma unroll
        for (int nt = 0; nt < 4; ++nt) {
            int row = row0 + wm * 32 + mt * 16 + g;
            int col = col0 + wn * 32 + nt * 8 + tg * 2;
#pragma unroll
            for (int hh = 0; hh < 2; ++hh) {
                __nv_bfloat162 hi, lo;
                split2(acc[mt][nt][2 * hh], acc[mt][nt][2 * hh + 1], hi, lo);
                size_t idx = (size_t)(row + hh * 8) * DD + col;
                *(__nv_bfloat162*)(g_Ah[z] + idx) = hi;
                *(__nv_bfloat162*)(g_Al[z] + idx) = lo;
            }
        }
}

// x_k = x @ A_k (A symmetric -> NT with B = A row-major [n][k])
__global__ void __launch_bounds__(512, 1) k_xk() {
    int z = blockIdx.z;
    if (z == 1 && g_same) return;
    int row0 = blockIdx.y << 7, col0 = blockIdx.x << 7;
    float acc[2][4][4] = {};
    gemm_main<false>(g_xh, g_xl, DD,
                     g_Ah[z], g_Al[z], DD,
                     DD, row0, col0, acc);
    int lane = threadIdx.x & 31, wid = threadIdx.x >> 5;
    int wm = wid & 3, wn = wid >> 2, g = lane >> 2, tg = lane & 3;
    __nv_bfloat16* Ch = g_xkh[z];
    __nv_bfloat16* Cl = g_xkl[z];
#pragma unroll
    for (int mt = 0; mt < 2; ++mt)
#pragma unroll
        for (int nt = 0; nt < 4; ++nt) {
            int row = row0 + wm * 32 + mt * 16 + g;
            int col = col0 + wn * 32 + nt * 8 + tg * 2;
#pragma unroll
            for (int hh = 0; hh < 2; ++hh) {
                __nv_bfloat162 hi, lo;
                split2(acc[mt][nt][2 * hh], acc[mt][nt][2 * hh + 1], hi, lo);
                size_t idx = (size_t)(row + hh * 8) * DD + col;
                *(__nv_bfloat162*)(Ch + idx) = hi;
                *(__nv_bfloat162*)(Cl + idx) = lo;
            }
        }
}

// scores (NT): s = scale * x_k[b] @ y[b]^T
__global__ void __launch_bounds__(512, 1) k_scores() {
    int z = blockIdx.z; int b = z >> 1; int k2 = z & 1;
    if (k2 == 1 && g_same) return;
    int row0 = blockIdx.y << 7, col0 = blockIdx.x << 7;
    float acc[2][4][4] = {};
    gemm_main<false>(g_xkh[k2] + (size_t)b * NQ * DD, g_xkl[k2] + (size_t)b * NQ * DD, DD,
                     g_yh + (size_t)b * MKV * DD, g_yl + (size_t)b * MKV * DD, DD,
                     DD, row0, col0, acc);
    int lane = threadIdx.x & 31, wid = threadIdx.x >> 5;
    int wm = wid & 3, wn = wid >> 2, g = lane >> 2, tg = lane & 3;
    float* C = g_s + (size_t)z * NQ * MKV;
#pragma unroll
    for (int mt = 0; mt < 2; ++mt)
#pragma unroll
        for (int nt = 0; nt < 4; ++nt) {
            int row = row0 + wm * 32 + mt * 16 + g;
            int col = col0 + wn * 32 + nt * 8 + tg * 2;
#pragma unroll
            for (int hh = 0; hh < 2; ++hh) {
                float2 v = make_float2(acc[mt][nt][2 * hh] * SCALE, acc[mt][nt][2 * hh + 1] * SCALE);
                *(float2*)(C + (size_t)(row + hh * 8) * MKV + col) = v;
            }
        }
}

// out = attn_c @ y (NN: B=[K][N]=y)
__global__ void __launch_bounds__(512, 1) k_av(float* __restrict__ out) {
    int b = blockIdx.z;
    int row0 = blockIdx.y << 7, col0 = blockIdx.x << 7;
    float acc[2][4][4] = {};
    gemm_main<true>(g_ach + (size_t)b * NQ * MKV, g_acl + (size_t)b * NQ * MKV, MKV,
                    g_yh + (size_t)b * MKV * DD, g_yl + (size_t)b * MKV * DD, DD,
                    MKV, row0, col0, acc);
    int lane = threadIdx.x & 31, wid = threadIdx.x >> 5;
    int wm = wid & 3, wn = wid >> 2, g = lane >> 2, tg = lane & 3;
    float* C = out + (size_t)b * NQ * DD;
#pragma unroll
    for (int mt = 0; mt < 2; ++mt)
#pragma unroll
        for (int nt = 0; nt < 4; ++nt) {
            int row = row0 + wm * 32 + mt * 16 + g;
            int col = col0 + wn * 32 + nt * 8 + tg * 2;
#pragma unroll
            for (int hh = 0; hh < 2; ++hh) {
                float2 v = make_float2(acc[mt][nt][2 * hh], acc[mt][nt][2 * hh + 1]);
                *(float2*)(C + (size_t)(row + hh * 8) * DD + col) = v;
            }
        }
}

// ---------------- K4: softmax + mix + entropy + route ----------------
__device__ __forceinline__ void blockReduce2(float& a, float& b, bool domax, float* red) {
#pragma unroll
    for (int o = 16; o; o >>= 1) {
        float ta = __shfl_xor_sync(0xffffffffu, a, o);
        float tb = __shfl_xor_sync(0xffffffffu, b, o);
        if (domax) { a = fmaxf(a, ta); b = fmaxf(b, tb); }
        else       { a += ta;          b += tb; }
    }
    int w = threadIdx.x >> 5, lane = threadIdx.x & 31;
    __syncthreads();
    if (lane == 0) { red[w] = a; red[8 + w] = b; }
    __syncthreads();
    a = red[0]; b = red[8];
#pragma unroll
    for (int i = 1; i < 8; ++i) {
        if (domax) { a = fmaxf(a, red[i]); b = fmaxf(b, red[8 + i]); }
        else       { a += red[i];          b += red[8 + i]; }
    }
}

__global__ void k_route(const float* __restrict__ gate, const float* __restrict__ temp,
                        float* __restrict__ heat_out) {
    int n = blockIdx.x, b = blockIdx.y;
    int tid = threadIdx.x;
    __shared__ float red[16];
    int same = g_same;
    const float* s1 = g_s + ((size_t)(b * 2 + 0) * NQ + n) * MKV;
    const float* s2 = g_s + ((size_t)(b * 2 + 1) * NQ + n) * MKV;
    const float* pp = g_pos + (size_t)n * MKV;
    int base = tid * 4;
    float4 V1 = *(const float4*)(s1 + base);
    float4 PV = *(const float4*)(pp + base);
    float v1[4] = {V1.x, V1.y, V1.z, V1.w};
    float pv[4] = {PV.x, PV.y, PV.z, PV.w};
    float gg = gate[0];
    float gsig = 1.f / (1.f + __expf(-gg));
    float og = 1.f - gsig;
    float tt = temp[0];
    size_t rowoff = ((size_t)b * NQ + n) * MKV;

    if (same) {
        float m1 = -1e30f, dummy = -1e30f;
#pragma unroll
        for (int i = 0; i < 4; ++i) m1 = fmaxf(m1, v1[i]);
        blockReduce2(m1, dummy, true, red);
        float e1 = 0.f, d2 = 0.f;
#pragma unroll
        for (int i = 0; i < 4; ++i) { v1[i] = __expf(v1[i] - m1); e1 += v1[i]; }
        blockReduce2(e1, d2, false, red);
        float r1 = __frcp_rn(e1);
        float ent1 = 0.f, d3 = 0.f;
#pragma unroll
        for (int i = 0; i < 4; ++i) {
            float a1 = og * v1[i] * r1 + gsig * pv[i];
            v1[i] = a1;
            ent1 -= a1 * __logf(a1 + 1e-8f);
        }
        blockReduce2(ent1, d3, false, red);
        float h1 = 2.f - 2.f / (1.f + __expf(-tt * ent1));
        if (tid == 0) heat_out[(size_t)b * NQ + n] = h1;
        __nv_bfloat162 h01, l01, h23, l23;
        split2(v1[0], v1[1], h01, l01);
        split2(v1[2], v1[3], h23, l23);
        *(__nv_bfloat162*)(g_ach + rowoff + base)     = h01;
        *(__nv_bfloat162*)(g_ach + rowoff + base + 2) = h23;
        *(__nv_bfloat162*)(g_acl + rowoff + base)     = l01;
        *(__nv_bfloat162*)(g_acl + rowoff + base + 2) = l23;
        return;
    }

    float4 V2 = *(const float4*)(s2 + base);
    float v2[4] = {V2.x, V2.y, V2.z, V2.w};
    float m1 = -1e30f, m2 = -1e30f;
#pragma unroll
    for (int i = 0; i < 4; ++i) { m1 = fmaxf(m1, v1[i]); m2 = fmaxf(m2, v2[i]); }
    blockReduce2(m1, m2, true, red);
    float e1 = 0.f, e2 = 0.f;
#pragma unroll
    for (int i = 0; i < 4; ++i) {
        v1[i] = __expf(v1[i] - m1); e1 += v1[i];
        v2[i] = __expf(v2[i] - m2); e2 += v2[i];
    }
    blockReduce2(e1, e2, false, red);
    float r1 = __frcp_rn(e1), r2 = __frcp_rn(e2);
    float ent1 = 0.f, ent2 = 0.f;
#pragma unroll
    for (int i = 0; i < 4; ++i) {
        float a1 = og * v1[i] * r1 + gsig * pv[i];
        float a2 = og * v2[i] * r2 + gsig * pv[i];
        v1[i] = a1; v2[i] = a2;
        ent1 -= a1 * __logf(a1 + 1e-8f);
        ent2 -= a2 * __logf(a2 + 1e-8f);
    }
    blockReduce2(ent1, ent2, false, red);
    float h1 = 2.f - 2.f / (1.f + __expf(-tt * ent1));
    float h2 = 2.f - 2.f / (1.f + __expf(-tt * ent2));
    bool fg = (h1 >= h2);
    if (tid == 0) heat_out[(size_t)b * NQ + n] = fg ? h1 : h2;
    __nv_bfloat162 h01, l01, h23, l23;
    float a0 = fg ? v1[0] : v2[0], a1 = fg ? v1[1] : v2[1];
    float a2 = fg ? v1[2] : v2[2], a3 = fg ? v1[3] : v2[3];
    split2(a0, a1, h01, l01);
    split2(a2, a3, h23, l23);
    *(__nv_bfloat162*)(g_ach + rowoff + base)     = h01;
    *(__nv_bfloat162*)(g_ach + rowoff + base + 2) = h23;
    *(__nv_bfloat162*)(g_acl + rowoff + base)     = l01;
    *(__nv_bfloat162*)(g_acl + rowoff + base + 2) = l23;
}

// ---------------- launch ----------------
extern "C" void kernel_launch(void* const* d_in, const int* in_sizes, int n_in,
                              void* d_out, int out_size) {
    const float* x      = (const float*)d_in[0];
    const float* y      = (const float*)d_in[1];
    const float* coords = (const float*)d_in[2];
    const float* U      = (const float*)d_in[3];
    const float* S1     = (const float*)d_in[4];
    const float* S2     = (const float*)d_in[5];
    const float* gating = (const float*)d_in[6];
    const float* temp   = (const float*)d_in[7];
    const float* pe     = (const float*)d_in[8];
    float* out  = (float*)d_out;                 // [B,N,D]
    float* heat = out + (size_t)BB * NQ * DD;    // [B,N,1]

    cudaFuncSetAttribute(k_buildA, cudaFuncAttributeMaxDynamicSharedMemorySize, 122880);
    cudaFuncSetAttribute(k_xk,     cudaFuncAttributeMaxDynamicSharedMemorySize, 122880);
    cudaFuncSetAttribute(k_scores, cudaFuncAttributeMaxDynamicSharedMemorySize, 122880);
    cudaFuncSetAttribute(k_av,     cudaFuncAttributeMaxDynamicSharedMemorySize, 113664);

    __nv_bfloat16 *xh, *xl, *yh, *yl;
    cudaGetSymbolAddress((void**)&xh, g_xh);
    cudaGetSymbolAddress((void**)&xl, g_xl);
    cudaGetSymbolAddress((void**)&yh, g_yh);
    cudaGetSymbolAddress((void**)&yl, g_yl);

    int n4 = BB * NQ * DD / 4;
    k_flag<<<1, 256>>>(S1, S2);
    k_cvt<<<(n4 + 255) / 256, 256>>>((const float4*)x, (__nv_bfloat162*)xh, (__nv_bfloat162*)xl, n4);
    k_cvt<<<(n4 + 255) / 256, 256>>>((const float4*)y, (__nv_bfloat162*)yh, (__nv_bfloat162*)yl, n4);
    k_prepU<<<dim3(DD / 32, DD / 32), dim3(32, 8)>>>(U, S1, S2);
    k_pos<<<dim3(NQ), 256>>>(coords, pe);
    k_buildA<<<dim3(DD / 128, DD / 128, 2), 512, 122880>>>();
    k_xk    <<<dim3(DD / 128, BB * NQ / 128, 2), 512, 122880>>>();
    k_scores<<<dim3(MKV / 128, NQ / 128, BB * 2), 512, 122880>>>();
    k_route <<<dim3(NQ, BB), 256>>>(gating, temp, heat);
    k_av    <<<dim3(DD / 128, NQ / 128, BB), 512, 113664>>>(out);
}